// round 9
// baseline (speedup 1.0000x reference)
#include <cuda_runtime.h>
#include <cuda_fp16.h>
#include <cstdint>

#define F_ 32
#define B_ 4096
#define D_ 64
#define K_ 512
#define NTHREADS 256

// ---------------- device scratch ----------------
__device__ __half g_wh1[(size_t)F_ * K_ * D_];  // fp16 limb1, [f][k][d]
__device__ __half g_wh2[(size_t)F_ * K_ * D_];  // fp16 limb2, [f][k][d]
__device__ float  g_wn [F_ * K_];               // 0.5*||w_k||^2
__device__ float  g_partial[1024];
__device__ int    g_count;

__device__ __forceinline__ uint32_t smem_u32(const void* p) {
    uint32_t a;
    asm("{ .reg .u64 t; cvta.to.shared.u64 t, %1; cvt.u32.u64 %0, t; }"
        : "=r"(a) : "l"(p));
    return a;
}

#define LDSM_X4(r_, addr_) \
    asm volatile("ldmatrix.sync.aligned.m8n8.x4.shared.b16 {%0,%1,%2,%3}, [%4];" \
        : "=r"((r_)[0]), "=r"((r_)[1]), "=r"((r_)[2]), "=r"((r_)[3]) : "r"(addr_))

#define CP_ASYNC16(dst_, src_) \
    asm volatile("cp.async.cg.shared.global [%0], [%1], 16;" :: "r"(dst_), "l"(src_))
#define CP_COMMIT() asm volatile("cp.async.commit_group;" ::: "memory")
#define CP_WAIT0()  asm volatile("cp.async.wait_group 0;" ::: "memory")

// fp16 x fp16 -> fp32 accumulate (main product)
__device__ __forceinline__ void mma_f16_f32(float* c, const uint32_t* a,
                                            const uint32_t* b) {
    asm volatile(
        "mma.sync.aligned.m16n8k16.row.col.f32.f16.f16.f32 "
        "{%0,%1,%2,%3}, {%4,%5,%6,%7}, {%8,%9}, {%0,%1,%2,%3};"
        : "+f"(c[0]), "+f"(c[1]), "+f"(c[2]), "+f"(c[3])
        : "r"(a[0]), "r"(a[1]), "r"(a[2]), "r"(a[3]), "r"(b[0]), "r"(b[1]));
}
// fp16 x fp16 -> fp16 accumulate (small correction products)
__device__ __forceinline__ void mma_f16_f16(uint32_t* c, const uint32_t* a,
                                            const uint32_t* b) {
    asm volatile(
        "mma.sync.aligned.m16n8k16.row.col.f16.f16.f16.f16 "
        "{%0,%1}, {%2,%3,%4,%5}, {%6,%7}, {%0,%1};"
        : "+r"(c[0]), "+r"(c[1])
        : "r"(a[0]), "r"(a[1]), "r"(a[2]), "r"(a[3]), "r"(b[0]), "r"(b[1]));
}

__device__ __forceinline__ uint32_t pack_h2(__half a, __half b) {
    __half2 h = __halves2half2(a, b);
    return *(uint32_t*)&h;
}

// smem (bytes). 128B rows + SW128 XOR swizzle: phys = row*128 + (col ^ ((row&7)<<4))
#define OFF_WNS  0
#define OFF_SIDX 2048
#define OFF_RED8 2560
#define OFF_X1   4096
#define OFF_X2   20480
#define OFF_WS   36864
#define SMEM_BYTES 69632

// ---------------------------------------------------------------------------
// Prep: transpose + fp16 2-limb split + norms. grid (16, 32) x 256.
// ---------------------------------------------------------------------------
__global__ void vq_prep(const float* __restrict__ w) {
    __shared__ float ts[32][65];
    __shared__ float ps[32][9];
    const int f = blockIdx.y, kt = blockIdx.x, tid = threadIdx.x;
    const float* wf = w + (size_t)f * D_ * K_ + kt * 32;

    for (int i = tid; i < 64 * 32; i += 256) {
        int d = i >> 5, kk = i & 31;
        ts[kk][d] = wf[(size_t)d * K_ + kk];
    }
    __syncthreads();

    size_t base = ((size_t)f * K_ + (size_t)kt * 32) * D_;
    for (int i = tid; i < 32 * 64; i += 256) {
        int kk = i >> 6, d = i & 63;
        float v = ts[kk][d];
        __half h1 = __float2half_rn(v);
        __half h2 = __float2half_rn(v - __half2float(h1));
        g_wh1[base + i] = h1;
        g_wh2[base + i] = h2;
    }
    {
        int kk = tid >> 3, seg = tid & 7;
        float s = 0.f;
#pragma unroll
        for (int d8 = 0; d8 < 8; ++d8) {
            float v = ts[kk][seg * 8 + d8];
            s += v * v;
        }
        ps[kk][seg] = s;
    }
    __syncthreads();
    if (tid < 32) {
        float s = 0.f;
#pragma unroll
        for (int g = 0; g < 8; ++g) s += ps[tid][g];
        g_wn[f * K_ + kt * 32 + tid] = 0.5f * s;
    }
}

// ---------------------------------------------------------------------------
// Main: hybrid-precision 3-product mma.sync (hh in f32-acc, hl+lh in f16-acc),
// cp.async double-buffered 64-code chunks, fused argmax+gather+loss.
// ---------------------------------------------------------------------------
__global__ __launch_bounds__(NTHREADS, 3)
void vq_main(const float* __restrict__ x, float* __restrict__ out,
             int loss_pos) {
    extern __shared__ __align__(1024) char smem[];
    const uint32_t sb = smem_u32(smem);
    float* wns  = (float*)(smem + OFF_WNS);
    int*   sidx = (int*)(smem + OFF_SIDX);
    float* red8 = (float*)(smem + OFF_RED8);
    float* red_v = (float*)(smem + OFF_WS);
    int*   red_i = (int*)(smem + OFF_WS + 8192);

    const int f   = blockIdx.y;
    const int b0  = blockIdx.x * 128;
    const int tid = threadIdx.x;
    const int wid = tid >> 5;
    const int lane = tid & 31;
    const int tq = lane >> 2, tr = lane & 3;
    const int wm = wid >> 2,  wn = wid & 3;
    const int lq = lane & 7,  quad = lane >> 3;
    const uint32_t xorv = (uint32_t)lq << 4;

    const __half* wh1g = g_wh1 + ((size_t)f << 9) * D_;
    const __half* wh2g = g_wh2 + ((size_t)f << 9) * D_;

    // ---- prologue: cp.async chunk 0 (codes 0..63) into buf 0 ----
    {
#pragma unroll
        for (int t = 0; t < 4; ++t) {
            int i = tid + t * 256;
            int limb = i >> 9;
            int n    = (i >> 3) & 63;
            int ch   = i & 7;
            uint32_t dst = sb + OFF_WS + (uint32_t)limb * 8192
                         + (uint32_t)n * 128
                         + (((uint32_t)ch * 16) ^ ((uint32_t)(n & 7) << 4));
            const __half* src = (limb ? wh2g : wh1g) + (size_t)n * 64 + ch * 8;
            CP_ASYNC16(dst, src);
        }
        CP_COMMIT();
    }

    wns[tid]       = g_wn[(f << 9) + tid];
    wns[tid + 256] = g_wn[(f << 9) + tid + 256];

    // ---- x tile -> fp16 limbs, swizzled 128B rows ----
    const float* xg = x + ((size_t)f * B_ + b0) * D_;
#pragma unroll
    for (int t = 0; t < 8; ++t) {
        int i = tid + t * 256;
        int r = i >> 4, c4 = i & 15;
        float4 v = ((const float4*)(xg + (size_t)r * D_))[c4];
        __half h1[4], h2[4];
        float vv[4] = {v.x, v.y, v.z, v.w};
#pragma unroll
        for (int j = 0; j < 4; ++j) {
            h1[j] = __float2half_rn(vv[j]);
            h2[j] = __float2half_rn(vv[j] - __half2float(h1[j]));
        }
        uint32_t off = (uint32_t)r * 128
                     + (((uint32_t)c4 * 8) ^ ((uint32_t)(r & 7) << 4));
        *(uint2*)(smem + OFF_X1 + off) =
            make_uint2(pack_h2(h1[0], h1[1]), pack_h2(h1[2], h1[3]));
        *(uint2*)(smem + OFF_X2 + off) =
            make_uint2(pack_h2(h2[0], h2[1]), pack_h2(h2[2], h2[3]));
    }

    float best[8];
    int   bidx[8];
#pragma unroll
    for (int i = 0; i < 8; ++i) { best[i] = -1e30f; bidx[i] = 0; }

    const uint32_t aBase = sb + OFF_X1
        + (uint32_t)(wm * 64 + lq + ((quad & 1) << 3)) * 128;
    const uint32_t aColBase = (uint32_t)((quad >> 1) << 4);
    const uint32_t bRowOff = (uint32_t)(wn * 16 + lq) * 128;
    const uint32_t bColBase = (uint32_t)quad * 16;

    for (int c = 0; c < 8; ++c) {
        CP_WAIT0();
        __syncthreads();

        if (c < 7) {
            int cn = c + 1;
            uint32_t bufoff = (uint32_t)(cn & 1) * 16384;
#pragma unroll
            for (int t = 0; t < 4; ++t) {
                int i = tid + t * 256;
                int limb = i >> 9;
                int n    = (i >> 3) & 63;
                int ch   = i & 7;
                uint32_t dst = sb + OFF_WS + bufoff + (uint32_t)limb * 8192
                             + (uint32_t)n * 128
                             + (((uint32_t)ch * 16) ^ ((uint32_t)(n & 7) << 4));
                const __half* src = (limb ? wh2g : wh1g)
                                  + ((size_t)(cn * 64 + n)) * 64 + ch * 8;
                CP_ASYNC16(dst, src);
            }
            CP_COMMIT();
        }

        const uint32_t wsb = sb + OFF_WS + (uint32_t)(c & 1) * 16384;

        float    acc [4][2][4];     // f32 acc for h1*w1
        uint32_t acc16[4][2][2];    // f16 acc (half2 x2) for h1*w2 + h2*w1
#pragma unroll
        for (int i = 0; i < 4; ++i)
#pragma unroll
            for (int j = 0; j < 2; ++j) {
#pragma unroll
                for (int q = 0; q < 4; ++q) acc[i][j][q] = 0.f;
                acc16[i][j][0] = 0u; acc16[i][j][1] = 0u;
            }

#pragma unroll
        for (int kkp = 0; kkp < 2; ++kkp) {
            uint32_t bb1[2][4], bb2[2][4];
#pragma unroll
            for (int j = 0; j < 2; ++j) {
                uint32_t ba = wsb + bRowOff + (uint32_t)j * 1024
                            + ((bColBase + (uint32_t)kkp * 64) ^ xorv);
                LDSM_X4(bb1[j], ba);
                LDSM_X4(bb2[j], ba + 8192);
            }
#pragma unroll
            for (int kk2 = 0; kk2 < 2; ++kk2) {
                const int kreg = kk2 * 2;
                const uint32_t kcol = (uint32_t)(kkp * 2 + kk2) * 32;
#pragma unroll
                for (int i = 0; i < 4; ++i) {
                    uint32_t aa = aBase + (uint32_t)i * 2048
                                + ((aColBase + kcol) ^ xorv);
                    uint32_t a1[4], a2[4];
                    LDSM_X4(a1, aa);
                    LDSM_X4(a2, aa + 16384);
#pragma unroll
                    for (int j = 0; j < 2; ++j) {
                        mma_f16_f32(acc[i][j], a1, &bb1[j][kreg]);    // h1*w1 (f32)
                        mma_f16_f16(acc16[i][j], a1, &bb2[j][kreg]);  // h1*w2 (f16)
                        mma_f16_f16(acc16[i][j], a2, &bb1[j][kreg]);  // h2*w1 (f16)
                    }
                }
            }
        }

        // fold chunk scores into running argmax (k ascending; strict >)
#pragma unroll
        for (int j = 0; j < 2; ++j)
#pragma unroll
            for (int h = 0; h < 2; ++h) {
                float2 corr = __half22float2(*(__half2*)&acc16[0][0]);  // placeholder (overwritten below)
                (void)corr;
#pragma unroll
                for (int i = 0; i < 4; ++i) {
                    float2 cv = __half22float2(*(__half2*)&acc16[i][j][h]);
#pragma unroll
                    for (int c01 = 0; c01 < 2; ++c01) {
                        int kg = c * 64 + wn * 16 + j * 8 + tr * 2 + c01;
                        float s = acc[i][j][h * 2 + c01]
                                + (c01 ? cv.y : cv.x) - wns[kg];
                        int slot = i * 2 + h;
                        if (s > best[slot]) { best[slot] = s; bidx[slot] = kg; }
                    }
                }
            }
    }

    __syncthreads();   // all ws reads done; overlay reduction arrays

#pragma unroll
    for (int i = 0; i < 4; ++i)
#pragma unroll
        for (int h = 0; h < 2; ++h) {
            int row = wm * 64 + i * 16 + h * 8 + tq;
            red_v[row * 16 + wn * 4 + tr] = best[i * 2 + h];
            red_i[row * 16 + wn * 4 + tr] = bidx[i * 2 + h];
        }
    __syncthreads();

    if (tid < 128) {
        float bv = -1e30f;
        int bk = 0x7FFFFFFF;
#pragma unroll
        for (int t = 0; t < 16; ++t) {
            float v = red_v[tid * 16 + t];
            int  kk = red_i[tid * 16 + t];
            if (v > bv || (v == bv && kk < bk)) { bv = v; bk = kk; }
        }
        sidx[tid] = bk;
    }
    __syncthreads();

    // ---- gather (q = h1 + h2) + loss ----
    float lsum = 0.f;
    float* og = out + ((size_t)f * B_ + b0) * D_;
    for (int e = tid; e < 128 * D_; e += NTHREADS) {
        int r = e >> 6, d = e & 63;
        size_t gi = (size_t)sidx[r] * D_ + d;
        float q  = __half2float(wh1g[gi]) + __half2float(wh2g[gi]);
        float xv = xg[e];
        og[e] = q;
        float dif = q - xv;
        lsum += dif * dif;
    }
#pragma unroll
    for (int o = 16; o > 0; o >>= 1)
        lsum += __shfl_xor_sync(0xFFFFFFFFu, lsum, o);
    if ((tid & 31) == 0) red8[wid] = lsum;
    __syncthreads();

    __shared__ int s_last;
    if (tid == 0) {
        float t = 0.f;
#pragma unroll
        for (int i = 0; i < 8; ++i) t += red8[i];
        g_partial[blockIdx.y * gridDim.x + blockIdx.x] = t;
        __threadfence();
        int old = atomicAdd(&g_count, 1);
        s_last = (old == 1023) ? 1 : 0;
    }
    __syncthreads();

    if (s_last) {
        float s = 0.f;
#pragma unroll
        for (int t = 0; t < 4; ++t) s += g_partial[tid + t * 256];
#pragma unroll
        for (int o = 16; o > 0; o >>= 1)
            s += __shfl_xor_sync(0xFFFFFFFFu, s, o);
        if ((tid & 31) == 0) red8[wid] = s;
        __syncthreads();
        if (tid == 0) {
            float t = 0.f;
#pragma unroll
            for (int i = 0; i < 8; ++i) t += red8[i];
            out[loss_pos] = t * (1.25f / (float)(F_ * B_ * D_));
            g_count = 0;
        }
    }
}

// ---------------------------------------------------------------------------
extern "C" void kernel_launch(void* const* d_in, const int* in_sizes, int n_in,
                              void* d_out, int out_size) {
    const float* x = (const float*)d_in[0];   // (F,B,D)
    const float* w = (const float*)d_in[1];   // (F,D,K)
    float* out = (float*)d_out;

    cudaFuncSetAttribute(vq_main, cudaFuncAttributeMaxDynamicSharedMemorySize,
                         SMEM_BYTES);

    dim3 pgrid(16, 32);
    vq_prep<<<pgrid, 256>>>(w);

    dim3 grid(B_ / 128, F_);
    vq_main<<<grid, NTHREADS, SMEM_BYTES>>>(x, out, out_size - 1);
}

// round 10
// speedup vs baseline: 1.1152x; 1.1152x over previous
#include <cuda_runtime.h>
#include <cuda_fp16.h>
#include <cstdint>

#define F_ 32
#define B_ 4096
#define D_ 64
#define K_ 512
#define NTHREADS 256

// ---------------- device scratch ----------------
__device__ __half g_wh1[(size_t)F_ * K_ * D_];  // fp16 limb1, [f][k][d]
__device__ __half g_wh2[(size_t)F_ * K_ * D_];  // fp16 limb2, [f][k][d]
__device__ float  g_wn [F_ * K_];               // 0.5*||w_k||^2
__device__ float  g_partial[1024];
__device__ int    g_count;

__device__ __forceinline__ uint32_t smem_u32(const void* p) {
    uint32_t a;
    asm("{ .reg .u64 t; cvta.to.shared.u64 t, %1; cvt.u32.u64 %0, t; }"
        : "=r"(a) : "l"(p));
    return a;
}

#define LDSM_X4(r_, addr_) \
    asm volatile("ldmatrix.sync.aligned.m8n8.x4.shared.b16 {%0,%1,%2,%3}, [%4];" \
        : "=r"((r_)[0]), "=r"((r_)[1]), "=r"((r_)[2]), "=r"((r_)[3]) : "r"(addr_))

#define CP_ASYNC16(dst_, src_) \
    asm volatile("cp.async.cg.shared.global [%0], [%1], 16;" :: "r"(dst_), "l"(src_))
#define CP_COMMIT() asm volatile("cp.async.commit_group;" ::: "memory")
#define CP_WAIT0()  asm volatile("cp.async.wait_group 0;" ::: "memory")

__device__ __forceinline__ void mma_f16(float* c, const uint32_t* a,
                                        const uint32_t* b) {
    asm volatile(
        "mma.sync.aligned.m16n8k16.row.col.f32.f16.f16.f32 "
        "{%0,%1,%2,%3}, {%4,%5,%6,%7}, {%8,%9}, {%0,%1,%2,%3};"
        : "+f"(c[0]), "+f"(c[1]), "+f"(c[2]), "+f"(c[3])
        : "r"(a[0]), "r"(a[1]), "r"(a[2]), "r"(a[3]), "r"(b[0]), "r"(b[1]));
}

__device__ __forceinline__ uint32_t pack_h2(__half a, __half b) {
    __half2 h = __halves2half2(a, b);
    return *(uint32_t*)&h;
}

// smem (bytes). 128B rows + SW128 XOR swizzle: phys = row*128 + (col ^ ((row&7)<<4))
#define OFF_WNS  0
#define OFF_SIDX 2048
#define OFF_RED8 2560
#define OFF_X1   4096
#define OFF_X2   20480
#define OFF_WS   36864
#define SMEM_BYTES 69632

// ---------------------------------------------------------------------------
// Prep: transpose + fp16 2-limb split + norms. grid (16, 32) x 256.
// ---------------------------------------------------------------------------
__global__ void vq_prep(const float* __restrict__ w) {
    __shared__ float ts[32][65];
    __shared__ float ps[32][9];
    const int f = blockIdx.y, kt = blockIdx.x, tid = threadIdx.x;
    const float* wf = w + (size_t)f * D_ * K_ + kt * 32;

    for (int i = tid; i < 64 * 32; i += 256) {
        int d = i >> 5, kk = i & 31;
        ts[kk][d] = wf[(size_t)d * K_ + kk];
    }
    __syncthreads();

    size_t base = ((size_t)f * K_ + (size_t)kt * 32) * D_;
    for (int i = tid; i < 32 * 64; i += 256) {
        int kk = i >> 6, d = i & 63;
        float v = ts[kk][d];
        __half h1 = __float2half_rn(v);
        __half h2 = __float2half_rn(v - __half2float(h1));
        g_wh1[base + i] = h1;
        g_wh2[base + i] = h2;
    }
    {
        int kk = tid >> 3, seg = tid & 7;
        float s = 0.f;
#pragma unroll
        for (int d8 = 0; d8 < 8; ++d8) {
            float v = ts[kk][seg * 8 + d8];
            s += v * v;
        }
        ps[kk][seg] = s;
    }
    __syncthreads();
    if (tid < 32) {
        float s = 0.f;
#pragma unroll
        for (int g = 0; g < 8; ++g) s += ps[tid][g];
        g_wn[f * K_ + kt * 32 + tid] = 0.5f * s;
    }
}

// ---------------------------------------------------------------------------
// Main: fp16 3-product mma.sync, 32x32 warp tiles (4M x 2N), cp.async
// double-buffered 64-code chunks, fused argmax+gather+loss.
// ---------------------------------------------------------------------------
__global__ __launch_bounds__(NTHREADS, 3)
void vq_main(const float* __restrict__ x, float* __restrict__ out,
             int loss_pos) {
    extern __shared__ __align__(1024) char smem[];
    const uint32_t sb = smem_u32(smem);
    float* wns  = (float*)(smem + OFF_WNS);
    int*   sidx = (int*)(smem + OFF_SIDX);
    float* red8 = (float*)(smem + OFF_RED8);
    float* red_v = (float*)(smem + OFF_WS);           // [128][8] f32 = 4096 B
    int*   red_i = (int*)(smem + OFF_WS + 4096);      // [128][8] int

    const int f   = blockIdx.y;
    const int b0  = blockIdx.x * 128;
    const int tid = threadIdx.x;
    const int wid = tid >> 5;
    const int lane = tid & 31;
    const int tq = lane >> 2, tr = lane & 3;
    const int wm = wid >> 1,  wn = wid & 1;   // 4M x 2N warp grid
    const int lq = lane & 7,  quad = lane >> 3;
    const uint32_t xorv = (uint32_t)lq << 4;

    const __half* wh1g = g_wh1 + ((size_t)f << 9) * D_;
    const __half* wh2g = g_wh2 + ((size_t)f << 9) * D_;

    // ---- prologue: cp.async chunk 0 (codes 0..63) into buf 0 ----
    {
#pragma unroll
        for (int t = 0; t < 4; ++t) {
            int i = tid + t * 256;
            int limb = i >> 9;
            int n    = (i >> 3) & 63;
            int ch   = i & 7;
            uint32_t dst = sb + OFF_WS + (uint32_t)limb * 8192
                         + (uint32_t)n * 128
                         + (((uint32_t)ch * 16) ^ ((uint32_t)(n & 7) << 4));
            const __half* src = (limb ? wh2g : wh1g) + (size_t)n * 64 + ch * 8;
            CP_ASYNC16(dst, src);
        }
        CP_COMMIT();
    }

    wns[tid]       = g_wn[(f << 9) + tid];
    wns[tid + 256] = g_wn[(f << 9) + tid + 256];

    // ---- x tile -> fp16 limbs, swizzled 128B rows ----
    const float* xg = x + ((size_t)f * B_ + b0) * D_;
#pragma unroll
    for (int t = 0; t < 8; ++t) {
        int i = tid + t * 256;
        int r = i >> 4, c4 = i & 15;
        float4 v = ((const float4*)(xg + (size_t)r * D_))[c4];
        __half h1[4], h2[4];
        float vv[4] = {v.x, v.y, v.z, v.w};
#pragma unroll
        for (int j = 0; j < 4; ++j) {
            h1[j] = __float2half_rn(vv[j]);
            h2[j] = __float2half_rn(vv[j] - __half2float(h1[j]));
        }
        uint32_t off = (uint32_t)r * 128
                     + (((uint32_t)c4 * 8) ^ ((uint32_t)(r & 7) << 4));
        *(uint2*)(smem + OFF_X1 + off) =
            make_uint2(pack_h2(h1[0], h1[1]), pack_h2(h1[2], h1[3]));
        *(uint2*)(smem + OFF_X2 + off) =
            make_uint2(pack_h2(h2[0], h2[1]), pack_h2(h2[2], h2[3]));
    }

    float best[4];
    int   bidx[4];
#pragma unroll
    for (int i = 0; i < 4; ++i) { best[i] = -1e30f; bidx[i] = 0; }

    const uint32_t aBase = sb + OFF_X1
        + (uint32_t)(wm * 32 + lq + ((quad & 1) << 3)) * 128;
    const uint32_t aColBase = (uint32_t)((quad >> 1) << 4);
    const uint32_t bRowOff = (uint32_t)(wn * 32 + lq) * 128;
    const uint32_t bColBase = (uint32_t)quad * 16;

    for (int c = 0; c < 8; ++c) {
        CP_WAIT0();
        __syncthreads();

        if (c < 7) {
            int cn = c + 1;
            uint32_t bufoff = (uint32_t)(cn & 1) * 16384;
#pragma unroll
            for (int t = 0; t < 4; ++t) {
                int i = tid + t * 256;
                int limb = i >> 9;
                int n    = (i >> 3) & 63;
                int ch   = i & 7;
                uint32_t dst = sb + OFF_WS + bufoff + (uint32_t)limb * 8192
                             + (uint32_t)n * 128
                             + (((uint32_t)ch * 16) ^ ((uint32_t)(n & 7) << 4));
                const __half* src = (limb ? wh2g : wh1g)
                                  + ((size_t)(cn * 64 + n)) * 64 + ch * 8;
                CP_ASYNC16(dst, src);
            }
            CP_COMMIT();
        }

        const uint32_t wsb = sb + OFF_WS + (uint32_t)(c & 1) * 16384;

        float acc[2][4][4];
#pragma unroll
        for (int i = 0; i < 2; ++i)
#pragma unroll
            for (int j = 0; j < 4; ++j)
#pragma unroll
                for (int q = 0; q < 4; ++q) acc[i][j][q] = 0.f;

#pragma unroll
        for (int kkp = 0; kkp < 2; ++kkp) {
            uint32_t bb1[4][4], bb2[4][4];
#pragma unroll
            for (int j = 0; j < 4; ++j) {
                uint32_t ba = wsb + bRowOff + (uint32_t)j * 1024
                            + ((bColBase + (uint32_t)kkp * 64) ^ xorv);
                LDSM_X4(bb1[j], ba);
                LDSM_X4(bb2[j], ba + 8192);
            }
#pragma unroll
            for (int kk2 = 0; kk2 < 2; ++kk2) {
                const int kreg = kk2 * 2;
                const uint32_t kcol = (uint32_t)(kkp * 2 + kk2) * 32;
#pragma unroll
                for (int i = 0; i < 2; ++i) {
                    uint32_t aa = aBase + (uint32_t)i * 2048
                                + ((aColBase + kcol) ^ xorv);
                    uint32_t a1[4], a2[4];
                    LDSM_X4(a1, aa);
                    LDSM_X4(a2, aa + 16384);
#pragma unroll
                    for (int j = 0; j < 4; ++j) {
                        mma_f16(acc[i][j], a1, bb1[j] + kreg);  // h1*w1
                        mma_f16(acc[i][j], a1, bb2[j] + kreg);  // h1*w2
                        mma_f16(acc[i][j], a2, bb1[j] + kreg);  // h2*w1
                    }
                }
            }
        }

        // fold chunk scores into running argmax (k ascending; strict >)
#pragma unroll
        for (int j = 0; j < 4; ++j)
#pragma unroll
            for (int c01 = 0; c01 < 2; ++c01) {
                int kg = c * 64 + wn * 32 + j * 8 + tr * 2 + c01;
                float wnv = wns[kg];
#pragma unroll
                for (int i = 0; i < 2; ++i)
#pragma unroll
                    for (int h = 0; h < 2; ++h) {
                        float s = acc[i][j][h * 2 + c01] - wnv;
                        int slot = i * 2 + h;
                        if (s > best[slot]) { best[slot] = s; bidx[slot] = kg; }
                    }
            }
    }

    __syncthreads();   // all ws reads done; overlay reduction arrays

#pragma unroll
    for (int i = 0; i < 2; ++i)
#pragma unroll
        for (int h = 0; h < 2; ++h) {
            int row = wm * 32 + i * 16 + h * 8 + tq;
            red_v[row * 8 + wn * 4 + tr] = best[i * 2 + h];
            red_i[row * 8 + wn * 4 + tr] = bidx[i * 2 + h];
        }
    __syncthreads();

    if (tid < 128) {
        float bv = -1e30f;
        int bk = 0x7FFFFFFF;
#pragma unroll
        for (int t = 0; t < 8; ++t) {
            float v = red_v[tid * 8 + t];
            int  kk = red_i[tid * 8 + t];
            if (v > bv || (v == bv && kk < bk)) { bv = v; bk = kk; }
        }
        sidx[tid] = bk;
    }
    __syncthreads();

    // ---- gather (q = h1 + h2) + loss ----
    float lsum = 0.f;
    float* og = out + ((size_t)f * B_ + b0) * D_;
    for (int e = tid; e < 128 * D_; e += NTHREADS) {
        int r = e >> 6, d = e & 63;
        size_t gi = (size_t)sidx[r] * D_ + d;
        float q  = __half2float(wh1g[gi]) + __half2float(wh2g[gi]);
        float xv = xg[e];
        og[e] = q;
        float dif = q - xv;
        lsum += dif * dif;
    }
#pragma unroll
    for (int o = 16; o > 0; o >>= 1)
        lsum += __shfl_xor_sync(0xFFFFFFFFu, lsum, o);
    if ((tid & 31) == 0) red8[wid] = lsum;
    __syncthreads();

    __shared__ int s_last;
    if (tid == 0) {
        float t = 0.f;
#pragma unroll
        for (int i = 0; i < 8; ++i) t += red8[i];
        g_partial[blockIdx.y * gridDim.x + blockIdx.x] = t;
        __threadfence();
        int old = atomicAdd(&g_count, 1);
        s_last = (old == 1023) ? 1 : 0;
    }
    __syncthreads();

    if (s_last) {
        float s = 0.f;
#pragma unroll
        for (int t = 0; t < 4; ++t) s += g_partial[tid + t * 256];
#pragma unroll
        for (int o = 16; o > 0; o >>= 1)
            s += __shfl_xor_sync(0xFFFFFFFFu, s, o);
        if ((tid & 31) == 0) red8[wid] = s;
        __syncthreads();
        if (tid == 0) {
            float t = 0.f;
#pragma unroll
            for (int i = 0; i < 8; ++i) t += red8[i];
            out[loss_pos] = t * (1.25f / (float)(F_ * B_ * D_));
            g_count = 0;
        }
    }
}

// ---------------------------------------------------------------------------
extern "C" void kernel_launch(void* const* d_in, const int* in_sizes, int n_in,
                              void* d_out, int out_size) {
    const float* x = (const float*)d_in[0];   // (F,B,D)
    const float* w = (const float*)d_in[1];   // (F,D,K)
    float* out = (float*)d_out;

    cudaFuncSetAttribute(vq_main, cudaFuncAttributeMaxDynamicSharedMemorySize,
                         SMEM_BYTES);

    dim3 pgrid(16, 32);
    vq_prep<<<pgrid, 256>>>(w);

    dim3 grid(B_ / 128, F_);
    vq_main<<<grid, NTHREADS, SMEM_BYTES>>>(x, out, out_size - 1);
}